// round 16
// baseline (speedup 1.0000x reference)
#include <cuda_runtime.h>
#include <cuda_bf16.h>
#include <math.h>
#include <stdint.h>

#define NB 1024
#define NS 100
#define NH 256
#define NL 20000
#define NU 20000
#define NEL 500000
#define NEU 400000

// ---------------- scratch (float units) --------------------------------------
#define OFF_ENCW 0ull
#define OFF_EWU  (OFF_ENCW + (size_t)NL * NH)
#define OFF_XEH  (OFF_EWU  + (size_t)NU * NH)
#define OFF_XEM  (OFF_XEH  + (size_t)NB * NS * NH / 2)
#define OFF_XP   (OFF_XEM  + (size_t)NB * NS * NH / 2)
#define OFF_W1H  (OFF_XP   + (size_t)NB * NS * NH)
#define OFF_W1M  (OFF_W1H  + (size_t)NL * 3 * NH / 2)
#define OFF_WIHH (OFF_W1M  + (size_t)NL * 3 * NH / 2)
#define OFF_WIHM (OFF_WIHH + (size_t)NH * NH / 2)
#define OFF_WHHH (OFF_WIHM + (size_t)NH * NH / 2)
#define OFF_WHHM (OFF_WHHH + (size_t)NH * NH / 2)
#define OFF_FH   (OFF_WHHM + (size_t)NH * NH / 2)
#define OFF_FM   (OFF_FH   + (size_t)NB * 3 * NH / 2)
#define OFF_SIM  (OFF_FM   + (size_t)NB * 3 * NH / 2)
#define OFF_WN   (OFF_SIM  + (size_t)NB * NS)
#define OFF_NEED (OFF_WN   + (size_t)NB * NS)
#define OFF_LIST (OFF_NEED + (size_t)NU)
#define OFF_CNT  (OFF_LIST + (size_t)NEU)
#define SCRATCH_FLOATS (OFF_CNT + 4)

__device__ __align__(16) float g_scratch[SCRATCH_FLOATS];

// ---------------- PTX helpers -----------------------------------------------
__device__ __forceinline__ uint32_t smem_u32(const void* p) {
    uint32_t a;
    asm("{ .reg .u64 t; cvta.to.shared.u64 t, %1; cvt.u32.u64 %0, t; }" : "=r"(a) : "l"(p));
    return a;
}
#define SWZ128(o) ((o) ^ (((o) >> 3) & 0x70))

#define LDSM4(r, a) \
    asm volatile("ldmatrix.sync.aligned.m8n8.x4.shared.b16 {%0,%1,%2,%3}, [%4];" \
        : "=r"((r)[0]), "=r"((r)[1]), "=r"((r)[2]), "=r"((r)[3]) : "r"(a))

#define MMA_BF16(d, a, b) \
    asm volatile("mma.sync.aligned.m16n8k16.row.col.f32.bf16.bf16.f32 " \
        "{%0,%1,%2,%3}, {%4,%5,%6,%7}, {%8,%9}, {%0,%1,%2,%3};" \
        : "+f"((d)[0]), "+f"((d)[1]), "+f"((d)[2]), "+f"((d)[3]) \
        : "r"((a)[0]), "r"((a)[1]), "r"((a)[2]), "r"((a)[3]), "r"((b)[0]), "r"((b)[1]))

__device__ __forceinline__ void cp16(uint32_t dst, const void* src, bool ok) {
    asm volatile("cp.async.cg.shared.global [%0], [%1], 16, %2;"
                 :: "r"(dst), "l"(src), "r"(ok ? 16 : 0) : "memory");
}
__device__ __forceinline__ void cp_commit() { asm volatile("cp.async.commit_group;" ::: "memory"); }
__device__ __forceinline__ void cp_wait2()  { asm volatile("cp.async.wait_group 2;" ::: "memory"); }
__device__ __forceinline__ void cp_wait1()  { asm volatile("cp.async.wait_group 1;" ::: "memory"); }
__device__ __forceinline__ void cp_wait0()  { asm volatile("cp.async.wait_group 0;" ::: "memory"); }
#define CLUSTER_SYNC() do { \
    asm volatile("barrier.cluster.arrive.aligned;" ::: "memory"); \
    asm volatile("barrier.cluster.wait.aligned;" ::: "memory"); \
} while (0)

// ---------------- small kernels ----------------------------------------------
__global__ void mark_k(const int* __restrict__ uid, int* __restrict__ needed, int* __restrict__ count) {
    int i = blockIdx.x * blockDim.x + threadIdx.x;
    if (i == 0) *count = 0;
    if (i < NB) needed[uid[i]] = 1;
}
__global__ void compact_k(const int* __restrict__ row, const int* __restrict__ needed,
                          int* __restrict__ list, int* __restrict__ count) {
    int e = blockIdx.x * blockDim.x + threadIdx.x;
    bool keep = false;
    if (e < NEU) keep = (needed[row[e]] != 0);
    unsigned mask = __ballot_sync(0xFFFFFFFFu, keep);
    if (keep) {
        int lane = threadIdx.x & 31;
        int leader = __ffs(mask) - 1;
        int base = 0;
        if (lane == leader) base = atomicAdd(count, __popc(mask));
        base = __shfl_sync(mask, base, leader);
        list[base + __popc(mask & ((1u << lane) - 1))] = e;
    }
}
__global__ void split3_k(const float* __restrict__ a, const float* __restrict__ b,
                         const float* __restrict__ c,
                         __nv_bfloat16* __restrict__ ah, __nv_bfloat16* __restrict__ am,
                         __nv_bfloat16* __restrict__ bh, __nv_bfloat16* __restrict__ bm,
                         __nv_bfloat16* __restrict__ ch, __nv_bfloat16* __restrict__ cm) {
    int i = blockIdx.x * blockDim.x + threadIdx.x;
    const int NA = NH * NH, NBB = NH * NH, NC = NL * 3 * NH;
    const float* src;
    __nv_bfloat16 *hi, *mi;
    int j;
    if (i < NA) { src = a; hi = ah; mi = am; j = i; }
    else if (i < NA + NBB) { src = b; hi = bh; mi = bm; j = i - NA; }
    else if (i < NA + NBB + NC) { src = c; hi = ch; mi = cm; j = i - NA - NBB; }
    else return;
    float x = src[j];
    __nv_bfloat16 h = __float2bfloat16(x);
    hi[j] = h;
    mi[j] = __float2bfloat16(x - __bfloat162float(h));
}

// ---------------- loc scatter: 32 threads/edge, 8 floats/thread -------------
__global__ void scatter_loc_k(const int* __restrict__ row, const int* __restrict__ col,
                              const float* __restrict__ vals, const float* __restrict__ emb,
                              float* __restrict__ out) {
    int t = blockIdx.x * blockDim.x + threadIdx.x;
    int e = t >> 5;
    if (e >= NEL) return;
    int q = (t & 31) << 2;
    int r = row[e], cl = col[e];
    float v = vals[e];
    const float* src = emb + (size_t)cl * NH + q;
    float* dst = out + (size_t)r * NH + q;
    float4 x0 = *(const float4*)(src);
    float4 x1 = *(const float4*)(src + 128);
    asm volatile("red.global.add.v4.f32 [%0], {%1, %2, %3, %4};"
                 :: "l"(dst), "f"(v * x0.x), "f"(v * x0.y), "f"(v * x0.z), "f"(v * x0.w) : "memory");
    asm volatile("red.global.add.v4.f32 [%0], {%1, %2, %3, %4};"
                 :: "l"(dst + 128), "f"(v * x1.x), "f"(v * x1.y), "f"(v * x1.z), "f"(v * x1.w) : "memory");
}
__global__ void scatter_usr_c(const int* __restrict__ row, const int* __restrict__ col,
                              const float* __restrict__ vals, const float* __restrict__ emb,
                              float* __restrict__ out, const int* __restrict__ list,
                              const int* __restrict__ count) {
    int n = *count;
    int nb = (n + 3) >> 2;
    int sub = threadIdx.x >> 6;
    int q = (threadIdx.x & 63) << 2;
    for (int b = blockIdx.x; b < nb; b += gridDim.x) {
        int idx = b * 4 + sub;
        if (idx >= n) continue;
        int e = list[idx];
        int r = row[e], cl = col[e];
        float v = vals[e];
        float4 x = *(const float4*)(emb + (size_t)cl * NH + q);
        float* dst = out + (size_t)r * NH + q;
        asm volatile("red.global.add.v4.f32 [%0], {%1, %2, %3, %4};"
                     :: "l"(dst), "f"(v * x.x), "f"(v * x.y), "f"(v * x.z), "f"(v * x.w) : "memory");
    }
}

// ---------------- gather x_emb (bf16 splits) + similarity -------------------
__global__ void gather_sim_k(const int* __restrict__ fsm, const int* __restrict__ uid,
                             const float* __restrict__ encw, const float* __restrict__ ewu,
                             __nv_bfloat16* __restrict__ xeh, __nv_bfloat16* __restrict__ xem,
                             float* __restrict__ sim) {
    int tid = threadIdx.x;
    int lane = tid & 31;
    int pair = blockIdx.x * 8 + (tid >> 5);
    int b = pair / NS;
    int loc = fsm[pair];
    const float* xr = encw + (size_t)loc * NH + lane * 8;
    const float* ur = ewu + (size_t)uid[b] * NH + lane * 8;
    float ss = 0.0f;
#pragma unroll
    for (int g = 0; g < 2; g++) {
        float4 x = *(const float4*)(xr + g * 4);
        float4 u = *(const float4*)(ur + g * 4);
        float xv[4] = {x.x, x.y, x.z, x.w};
        float uv[4] = {u.x, u.y, u.z, u.w};
        __nv_bfloat16 hh[4], mm[4];
#pragma unroll
        for (int j = 0; j < 4; j++) {
            float d = uv[j] - xv[j];
            ss += d * d;
            hh[j] = __float2bfloat16(xv[j]);
            mm[j] = __float2bfloat16(xv[j] - __bfloat162float(hh[j]));
        }
        __nv_bfloat162 hp0; hp0.x = hh[0]; hp0.y = hh[1];
        __nv_bfloat162 hp1; hp1.x = hh[2]; hp1.y = hh[3];
        __nv_bfloat162 mp0; mp0.x = mm[0]; mp0.y = mm[1];
        __nv_bfloat162 mp1; mp1.x = mm[2]; mp1.y = mm[3];
        int cc = lane * 8 + g * 4;
        *(__nv_bfloat162*)(xeh + (size_t)pair * NH + cc) = hp0;
        *(__nv_bfloat162*)(xeh + (size_t)pair * NH + cc + 2) = hp1;
        *(__nv_bfloat162*)(xem + (size_t)pair * NH + cc) = mp0;
        *(__nv_bfloat162*)(xem + (size_t)pair * NH + cc + 2) = mp1;
    }
#pragma unroll
    for (int o = 16; o > 0; o >>= 1) ss += __shfl_xor_sync(0xFFFFFFFFu, ss, o);
    if (lane == 0) sim[pair] = expf(-sqrtf(ss));
}

// ---------------- decay weights ---------------------------------------------
__global__ void weights_k(const float* __restrict__ td, const float* __restrict__ gd,
                          const float* __restrict__ sim, const int* __restrict__ length,
                          float* __restrict__ wn) {
    int b = blockIdx.x;
    int s = threadIdx.x;
    __shared__ float red[128];
    float w = 0.0f;
    if (s < NS) {
        float t = td[b * NS + s];
        float a = (cosf(t * (6.2831853071795864769f / 86400.0f)) + 1.0f) * 0.5f
                  * expf(-t * (0.1f / 86400.0f));
        float bb = expf(-gd[b * NS + s] * 1000.0f);
        w = (a * bb + 1e-10f) * sim[b * NS + s];
        if (s >= length[b]) w = 0.0f;
    }
    red[s] = w;
    __syncthreads();
    for (int o = 64; o > 0; o >>= 1) {
        if (s < o) red[s] += red[s + o];
        __syncthreads();
    }
    float denom = red[0];
    if (s < NS) wn[b * NS + s] = w / denom;
}

// ---------------- mma.sync bf16x3 GEMM (3-stage pipeline) -------------------
#define STG_B 65536
#define SMEM_GEMM (3 * STG_B)

__global__ __launch_bounds__(256, 1)
void gemm3(const __nv_bfloat16* __restrict__ Ah, const __nv_bfloat16* __restrict__ Am,
           const __nv_bfloat16* __restrict__ Bh, const __nv_bfloat16* __restrict__ Bm,
           int Nlog, int K, float* __restrict__ C, const float* __restrict__ bias) {
    extern __shared__ char smem[];
    uint32_t sb = smem_u32(smem);
    int tid = threadIdx.x;
    int lane = tid & 31;
    int wid = tid >> 5;
    int wm = wid >> 2, wn = wid & 3;
    int m0 = blockIdx.x * 128;
    int n0 = blockIdx.y * 128;
    int nc = K >> 6;

    const __nv_bfloat16* bases[4] = {Ah, Am, Bh, Bm};
    auto load_chunk = [&](int stage, int c) {
#pragma unroll
        for (int i = 0; i < 16; i++) {
            int seg = tid + i * 256;
            int arr = seg >> 10;
            int rem = seg & 1023;
            int row = rem >> 3;
            int c16 = rem & 7;
            uint32_t dst = sb + stage * STG_B + arr * 16384 + SWZ128(row * 128 + c16 * 16);
            int rg = (arr < 2) ? (m0 + row) : (n0 + row);
            bool ok = (arr < 2) || (rg < Nlog);
            cp16(dst, bases[arr] + (size_t)rg * K + c * 64 + c16 * 8, ok);
        }
        cp_commit();
    };

    float acc[4][4][4];
#pragma unroll
    for (int a = 0; a < 4; a++)
#pragma unroll
        for (int b = 0; b < 4; b++)
#pragma unroll
            for (int d = 0; d < 4; d++) acc[a][b][d] = 0.0f;

    int lrow = lane & 15;
    int lchunk = lane >> 4;

    load_chunk(0, 0);
    load_chunk(1, 1);
    for (int c = 0; c < nc; c++) {
        if (c + 2 < nc) { load_chunk((c + 2) % 3, c + 2); cp_wait2(); }
        else if (c + 1 < nc) cp_wait1();
        else cp_wait0();
        __syncthreads();
        uint32_t stg = sb + (c % 3) * STG_B;
#pragma unroll
        for (int s = 0; s < 4; s++) {
            uint32_t ah[4][4], am[4][4];
#pragma unroll
            for (int mt = 0; mt < 4; mt++) {
                int r = wm * 64 + mt * 16 + lrow;
                uint32_t off = SWZ128(r * 128 + (s * 2 + lchunk) * 16);
                LDSM4(ah[mt], stg + off);
                LDSM4(am[mt], stg + 16384 + off);
            }
            uint32_t bh[4][2], bm[4][2];
#pragma unroll
            for (int g = 0; g < 2; g++) {
                int r = wn * 32 + g * 16 + lrow;
                uint32_t off = SWZ128(r * 128 + (s * 2 + lchunk) * 16);
                uint32_t q[4];
                LDSM4(q, stg + 32768 + off);
                bh[2 * g][0] = q[0]; bh[2 * g + 1][0] = q[1];
                bh[2 * g][1] = q[2]; bh[2 * g + 1][1] = q[3];
                LDSM4(q, stg + 49152 + off);
                bm[2 * g][0] = q[0]; bm[2 * g + 1][0] = q[1];
                bm[2 * g][1] = q[2]; bm[2 * g + 1][1] = q[3];
            }
#pragma unroll
            for (int mt = 0; mt < 4; mt++)
#pragma unroll
                for (int nt = 0; nt < 4; nt++) {
                    MMA_BF16(acc[mt][nt], ah[mt], bh[nt]);
                    MMA_BF16(acc[mt][nt], ah[mt], bm[nt]);
                    MMA_BF16(acc[mt][nt], am[mt], bh[nt]);
                }
        }
        __syncthreads();
    }

#pragma unroll
    for (int mt = 0; mt < 4; mt++) {
        int r0 = m0 + wm * 64 + mt * 16 + (lane >> 2);
#pragma unroll
        for (int nt = 0; nt < 4; nt++) {
            int nn = n0 + wn * 32 + nt * 8 + (lane & 3) * 2;
            if (nn < Nlog) {
                float b0 = bias[nn], b1 = bias[nn + 1];
                float2 v0 = make_float2(acc[mt][nt][0] + b0, acc[mt][nt][1] + b1);
                *(float2*)(C + (size_t)r0 * Nlog + nn) = v0;
                float2 v1 = make_float2(acc[mt][nt][2] + b0, acc[mt][nt][3] + b1);
                *(float2*)(C + (size_t)(r0 + 8) * Nlog + nn) = v1;
            }
        }
    }
}

// ---------------- clustered persistent RNN v3 (512 threads) -----------------
// 2-CTA clusters, rank r computes h cols [128r,128r+128); 16 warps, each owns
// an n8 tile (48 MMAs/warp/step) -> 4 warps/SMSP for issue overlap. Wh+Wm
// resident; one cluster barrier per step for the double-buffered h exchange.
#define R2_AH0 0
#define R2_AM0 8192
#define R2_AH1 16384
#define R2_AM1 24576
#define R2_WH  32768
#define R2_WM  (R2_WH + 65536)
#define R2_WNS (R2_WM + 65536)
#define SMEM_RNN2 (R2_WNS + 16 * NS * 4)

__global__ __launch_bounds__(512, 1)
void rnn_persist2(const __nv_bfloat16* __restrict__ whh_h, const __nv_bfloat16* __restrict__ whh_m,
                  const float* __restrict__ xp, const float* __restrict__ wn,
                  const float* __restrict__ b_hh, const float* __restrict__ h0,
                  __nv_bfloat16* __restrict__ fh, __nv_bfloat16* __restrict__ fm) {
    extern __shared__ char smem[];
    uint32_t sb = smem_u32(smem);
    int tid = threadIdx.x;
    int lane = tid & 31;
    int wid = tid >> 5;                 // 0..15, n8 tile per warp
    int par = wid & 1;                  // parity: q0/q2 vs q1/q3
    uint32_t rank;
    asm("mov.u32 %0, %%cluster_ctarank;" : "=r"(rank));
    int m0 = (blockIdx.x >> 1) * 16;
    int nhalf = rank * 128;
    float* wns = (float*)(smem + R2_WNS);

    uint32_t psb;
    asm("mapa.shared::cluster.u32 %0, %1, %2;" : "=r"(psb) : "r"(sb), "r"(rank ^ 1u));

    // resident Wh + Wm halves: rows [nhalf, nhalf+128), 4 K-chunks x 16KB each
#pragma unroll
    for (int i = 0; i < 8; i++) {
        int seg = tid + i * 512;
        int ch = seg >> 10;
        int rem = seg & 1023;
        int row = rem >> 3;
        int c16 = rem & 7;
        uint32_t off = ch * 16384 + SWZ128(row * 128 + c16 * 16);
        cp16(sb + R2_WH + off, whh_h + (size_t)(nhalf + row) * NH + ch * 64 + c16 * 8, true);
        cp16(sb + R2_WM + off, whh_m + (size_t)(nhalf + row) * NH + ch * 64 + c16 * 8, true);
    }
    cp_commit();

    for (int i = tid; i < 16 * NS; i += 512) {
        int r = i / NS, s = i % NS;
        wns[r * NS + s] = wn[(m0 + r) * NS + s];
    }
    for (int i = tid; i < 16 * NH; i += 512) {
        int r = i >> 8, cc = i & 255;
        float x = h0[(size_t)(m0 + r) * NH + cc];
        __nv_bfloat16 hh = __float2bfloat16(x);
        uint32_t off = (cc >> 6) * 2048 + SWZ128(r * 128 + (cc & 63) * 2);
        *(__nv_bfloat16*)(smem + R2_AH0 + off) = hh;
        *(__nv_bfloat16*)(smem + R2_AM0 + off) = __float2bfloat16(x - __bfloat162float(hh));
    }

    int ncol = nhalf + wid * 8 + (lane & 3) * 2;    // this thread's 2 cols
    float bias0 = b_hh[ncol], bias1 = b_hh[ncol + 1];

    cp_wait0();
    __syncthreads();

    float acc_out[4] = {0.0f, 0.0f, 0.0f, 0.0f};
    int lrow = lane & 15;
    int lchunk = lane >> 4;
    int r0 = lane >> 2;
    int wrow = (wid & ~1) * 8;          // pair-shared 16-row LDSM window

    for (int s = 0; s < NS; s++) {
        uint32_t abase = (s & 1) ? (uint32_t)R2_AH1 : (uint32_t)R2_AH0;
        uint32_t wbase = (s & 1) ? (uint32_t)R2_AH0 : (uint32_t)R2_AH1;
        float2 xpr0 = *(const float2*)(xp + ((size_t)(m0 + r0) * NS + s) * NH + ncol);
        float2 xpr1 = *(const float2*)(xp + ((size_t)(m0 + r0 + 8) * NS + s) * NH + ncol);
        float acc[4] = {0.0f, 0.0f, 0.0f, 0.0f};

#pragma unroll
        for (int c = 0; c < 4; c++) {
            uint32_t stWh = sb + R2_WH + c * 16384;
            uint32_t stWm = sb + R2_WM + c * 16384;
#pragma unroll
            for (int s4 = 0; s4 < 4; s4++) {
                uint32_t aoff = c * 2048 + SWZ128(lrow * 128 + (s4 * 2 + lchunk) * 16);
                uint32_t ah[4], am[4];
                LDSM4(ah, sb + abase + aoff);
                LDSM4(am, sb + abase + 8192 + aoff);
                uint32_t off = SWZ128((wrow + lrow) * 128 + (s4 * 2 + lchunk) * 16);
                uint32_t q[4], bh[2], bm[2];
                LDSM4(q, stWh + off);
                bh[0] = par ? q[1] : q[0];
                bh[1] = par ? q[3] : q[2];
                LDSM4(q, stWm + off);
                bm[0] = par ? q[1] : q[0];
                bm[1] = par ? q[3] : q[2];
                MMA_BF16(acc, ah, bh);
                MMA_BF16(acc, ah, bm);
                MMA_BF16(acc, am, bh);
            }
        }

        float w0 = wns[r0 * NS + s];
        float w1 = wns[(r0 + 8) * NS + s];
        float v00 = tanhf(acc[0] + xpr0.x + bias0);
        float v01 = tanhf(acc[1] + xpr0.y + bias1);
        float v10 = tanhf(acc[2] + xpr1.x + bias0);
        float v11 = tanhf(acc[3] + xpr1.y + bias1);
        acc_out[0] += v00 * w0;
        acc_out[1] += v01 * w0;
        acc_out[2] += v10 * w1;
        acc_out[3] += v11 * w1;
        __nv_bfloat16 h00 = __float2bfloat16(v00), h01 = __float2bfloat16(v01);
        __nv_bfloat16 h10 = __float2bfloat16(v10), h11 = __float2bfloat16(v11);
        __nv_bfloat162 p0; p0.x = h00; p0.y = h01;
        __nv_bfloat162 p1; p1.x = h10; p1.y = h11;
        __nv_bfloat162 q0; q0.x = __float2bfloat16(v00 - __bfloat162float(h00));
                           q0.y = __float2bfloat16(v01 - __bfloat162float(h01));
        __nv_bfloat162 q1; q1.x = __float2bfloat16(v10 - __bfloat162float(h10));
                           q1.y = __float2bfloat16(v11 - __bfloat162float(h11));
        uint32_t off0 = (ncol >> 6) * 2048 + SWZ128(r0 * 128 + (ncol & 63) * 2);
        uint32_t off1 = (ncol >> 6) * 2048 + SWZ128((r0 + 8) * 128 + (ncol & 63) * 2);
        uint32_t up0 = *(uint32_t*)&p0, up1 = *(uint32_t*)&p1;
        uint32_t uq0 = *(uint32_t*)&q0, uq1 = *(uint32_t*)&q1;
        *(uint32_t*)(smem + wbase + off0) = up0;
        *(uint32_t*)(smem + wbase + off1) = up1;
        *(uint32_t*)(smem + wbase + 8192 + off0) = uq0;
        *(uint32_t*)(smem + wbase + 8192 + off1) = uq1;
        asm volatile("st.shared::cluster.b32 [%0], %1;" :: "r"(psb + wbase + off0), "r"(up0) : "memory");
        asm volatile("st.shared::cluster.b32 [%0], %1;" :: "r"(psb + wbase + off1), "r"(up1) : "memory");
        asm volatile("st.shared::cluster.b32 [%0], %1;" :: "r"(psb + wbase + 8192 + off0), "r"(uq0) : "memory");
        asm volatile("st.shared::cluster.b32 [%0], %1;" :: "r"(psb + wbase + 8192 + off1), "r"(uq1) : "memory");
        CLUSTER_SYNC();
    }

    // write out_w into fh/fm cols [nhalf, nhalf+128)
#pragma unroll
    for (int rr = 0; rr < 2; rr++) {
        int m = m0 + r0 + rr * 8;
        float v0 = acc_out[rr * 2 + 0];
        float v1 = acc_out[rr * 2 + 1];
        __nv_bfloat16 h0b = __float2bfloat16(v0), h1b = __float2bfloat16(v1);
        fh[(size_t)m * 3 * NH + ncol] = h0b;
        fh[(size_t)m * 3 * NH + ncol + 1] = h1b;
        fm[(size_t)m * 3 * NH + ncol] = __float2bfloat16(v0 - __bfloat162float(h0b));
        fm[(size_t)m * 3 * NH + ncol + 1] = __float2bfloat16(v1 - __bfloat162float(h1b));
    }
}

// ---------------- fused out_w2 + p_u ----------------------------------------
__global__ void outw2_pu_k(const int* __restrict__ fseq, const float* __restrict__ emb2,
                           const float* __restrict__ wn, const int* __restrict__ uid,
                           const float* __restrict__ user_emb,
                           __nv_bfloat16* __restrict__ fh, __nv_bfloat16* __restrict__ fm) {
    int b = blockIdx.x;
    int h = threadIdx.x;
    float x = user_emb[(size_t)uid[b] * NH + h];
    __nv_bfloat16 ph = __float2bfloat16(x);
    fh[(size_t)b * 3 * NH + NH + h] = ph;
    fm[(size_t)b * 3 * NH + NH + h] = __float2bfloat16(x - __bfloat162float(ph));
    float acc = 0.0f;
    for (int s = 0; s < NS; s++) {
        int loc = fseq[b * NS + s];
        acc += emb2[(size_t)loc * NH + h] * wn[b * NS + s];
    }
    __nv_bfloat16 hh = __float2bfloat16(acc);
    fh[(size_t)b * 3 * NH + 2 * NH + h] = hh;
    fm[(size_t)b * 3 * NH + 2 * NH + h] = __float2bfloat16(acc - __bfloat162float(hh));
}

// ---------------- host launcher ---------------------------------------------
extern "C" void kernel_launch(void* const* d_in, const int* in_sizes, int n_in,
                              void* d_out, int out_size) {
    const int*   full_seq     = (const int*)d_in[0];
    const int*   full_seq_map = (const int*)d_in[1];
    const int*   length       = (const int*)d_in[2];
    const int*   user_id      = (const int*)d_in[3];
    const float* time_delta   = (const float*)d_in[4];
    const float* geo_delta    = (const float*)d_in[5];
    const float* enc_emb      = (const float*)d_in[6];
    const float* user_emb     = (const float*)d_in[7];
    const float* emb2         = (const float*)d_in[8];
    const int*   row_loc      = (const int*)d_in[9];
    const int*   col_loc      = (const int*)d_in[10];
    const float* vals_loc     = (const float*)d_in[11];
    const int*   row_usr      = (const int*)d_in[12];
    const int*   col_usr      = (const int*)d_in[13];
    const float* vals_usr     = (const float*)d_in[14];
    const float* W_ih         = (const float*)d_in[15];
    const float* W_hh         = (const float*)d_in[16];
    const float* b_ih         = (const float*)d_in[17];
    const float* b_hh         = (const float*)d_in[18];
    const float* W1           = (const float*)d_in[19];
    const float* b1           = (const float*)d_in[20];
    const float* h0           = (const float*)d_in[21];
    float* out = (float*)d_out;

    float* base = nullptr;
    cudaGetSymbolAddress((void**)&base, g_scratch);
    float* encw = base + OFF_ENCW;
    float* ewu  = base + OFF_EWU;
    __nv_bfloat16* xeh = (__nv_bfloat16*)(base + OFF_XEH);
    __nv_bfloat16* xem = (__nv_bfloat16*)(base + OFF_XEM);
    float* xp   = base + OFF_XP;
    __nv_bfloat16* w1h = (__nv_bfloat16*)(base + OFF_W1H);
    __nv_bfloat16* w1m = (__nv_bfloat16*)(base + OFF_W1M);
    __nv_bfloat16* wih = (__nv_bfloat16*)(base + OFF_WIHH);
    __nv_bfloat16* wim = (__nv_bfloat16*)(base + OFF_WIHM);
    __nv_bfloat16* whh = (__nv_bfloat16*)(base + OFF_WHHH);
    __nv_bfloat16* whm = (__nv_bfloat16*)(base + OFF_WHHM);
    __nv_bfloat16* fh  = (__nv_bfloat16*)(base + OFF_FH);
    __nv_bfloat16* fm  = (__nv_bfloat16*)(base + OFF_FM);
    float* sim  = base + OFF_SIM;
    float* wn   = base + OFF_WN;
    int*   needed = (int*)(base + OFF_NEED);
    int*   elist  = (int*)(base + OFF_LIST);
    int*   ecount = (int*)(base + OFF_CNT);

    static cudaStream_t s1 = nullptr, s2 = nullptr;
    static cudaEvent_t evRoot = nullptr, evA = nullptr, evB = nullptr, evC = nullptr, evD = nullptr;
    if (s1 == nullptr) {
        cudaStreamCreateWithFlags(&s1, cudaStreamNonBlocking);
        cudaStreamCreateWithFlags(&s2, cudaStreamNonBlocking);
        cudaEventCreateWithFlags(&evRoot, cudaEventDisableTiming);
        cudaEventCreateWithFlags(&evA, cudaEventDisableTiming);
        cudaEventCreateWithFlags(&evB, cudaEventDisableTiming);
        cudaEventCreateWithFlags(&evC, cudaEventDisableTiming);
        cudaEventCreateWithFlags(&evD, cudaEventDisableTiming);
        cudaFuncSetAttribute(gemm3, cudaFuncAttributeMaxDynamicSharedMemorySize, SMEM_GEMM);
        cudaFuncSetAttribute(rnn_persist2, cudaFuncAttributeMaxDynamicSharedMemorySize, SMEM_RNN2);
    }

    // s0: zero accumulators, then fork
    cudaMemsetAsync(encw, 0, 2 * (size_t)NL * NH * sizeof(float), 0);
    cudaMemsetAsync(needed, 0, (size_t)NU * sizeof(int), 0);
    cudaEventRecord(evRoot, 0);
    cudaStreamWaitEvent(s1, evRoot, 0);
    cudaStreamWaitEvent(s2, evRoot, 0);

    // s2: weight splits
    {
        int n = 2 * NH * NH + NL * 3 * NH;
        split3_k<<<(n + 255) / 256, 256, 0, s2>>>(W_ih, W_hh, W1, wih, wim, whh, whm, w1h, w1m);
    }
    // s1: loc scatter
    scatter_loc_k<<<(NEL * 32 + 255) / 256, 256, 0, s1>>>(row_loc, col_loc, vals_loc, enc_emb, encw);
    // s0: user-graph chain
    mark_k<<<(NB + 255) / 256, 256>>>(user_id, needed, ecount);
    compact_k<<<(NEU + 255) / 256, 256>>>(row_usr, needed, elist, ecount);
    scatter_usr_c<<<2048, 256>>>(row_usr, col_usr, vals_usr, enc_emb, ewu, elist, ecount);

    // join s1 (encw) then gather + weights
    cudaEventRecord(evA, s1);
    cudaStreamWaitEvent(0, evA, 0);
    gather_sim_k<<<NB * NS / 8, 256>>>(full_seq_map, user_id, encw, ewu, xeh, xem, sim);
    weights_k<<<NB, 128>>>(time_delta, geo_delta, sim, length, wn);

    // fork s1: outw2+pu (writes feat cols [NH, 3NH))
    cudaEventRecord(evB, 0);
    cudaStreamWaitEvent(s1, evB, 0);
    outw2_pu_k<<<NB, NH, 0, s1>>>(full_seq, emb2, wn, user_id, user_emb, fh, fm);

    // join s2 (weight splits) before the GEMMs
    cudaEventRecord(evC, s2);
    cudaStreamWaitEvent(0, evC, 0);

    // XP = x_emb @ W_ih^T + b_ih
    gemm3<<<dim3((NB * NS) / 128, 2), 256, SMEM_GEMM>>>(xeh, xem, wih, wim, NH, NH, xp, b_ih);

    // clustered persistent RNN v3 (128 CTAs x 512 threads, clusters of 2)
    {
        cudaLaunchConfig_t cfg = {};
        cfg.gridDim = dim3(NB / 16 * 2, 1, 1);
        cfg.blockDim = dim3(512, 1, 1);
        cfg.dynamicSmemBytes = SMEM_RNN2;
        cfg.stream = 0;
        cudaLaunchAttribute attrs[1];
        attrs[0].id = cudaLaunchAttributeClusterDimension;
        attrs[0].val.clusterDim = {2, 1, 1};
        cfg.attrs = attrs;
        cfg.numAttrs = 1;
        cudaLaunchKernelEx(&cfg, rnn_persist2, whh, whm, (const float*)xp, (const float*)wn,
                           b_hh, h0, fh, fm);
    }

    // join s1 (outw2_pu) before the final GEMM
    cudaEventRecord(evD, s1);
    cudaStreamWaitEvent(0, evD, 0);

    // final: out = feat @ W1^T + b1
    gemm3<<<dim3(NB / 128, (NL + 127) / 128), 256, SMEM_GEMM>>>(fh, fm, w1h, w1m, NL, 3 * NH, out, b1);
}

// round 17
// speedup vs baseline: 1.2782x; 1.2782x over previous
#include <cuda_runtime.h>
#include <cuda_bf16.h>
#include <math.h>
#include <stdint.h>

#define NB 1024
#define NS 100
#define NH 256
#define NL 20000
#define NLP 20096          // NL padded to multiple of 128 for GEMM tiles
#define NU 20000
#define NEL 500000
#define NEU 400000

// ---------------- scratch (float units) --------------------------------------
#define OFF_ENCW 0ull
#define OFF_EWU  (OFF_ENCW + (size_t)NL * NH)
#define OFF_ENCH (OFF_EWU  + (size_t)NU * NH)
#define OFF_ENCM (OFF_ENCH + (size_t)NLP * NH / 2)
#define OFF_ENCP (OFF_ENCM + (size_t)NLP * NH / 2)
#define OFF_W1H  (OFF_ENCP + (size_t)NLP * NH)
#define OFF_W1M  (OFF_W1H  + (size_t)NL * 3 * NH / 2)
#define OFF_WIHH (OFF_W1M  + (size_t)NL * 3 * NH / 2)
#define OFF_WIHM (OFF_WIHH + (size_t)NH * NH / 2)
#define OFF_WHHH (OFF_WIHM + (size_t)NH * NH / 2)
#define OFF_WHHM (OFF_WHHH + (size_t)NH * NH / 2)
#define OFF_FH   (OFF_WHHM + (size_t)NH * NH / 2)
#define OFF_FM   (OFF_FH   + (size_t)NB * 3 * NH / 2)
#define OFF_SIM  (OFF_FM   + (size_t)NB * 3 * NH / 2)
#define OFF_WN   (OFF_SIM  + (size_t)NB * NS)
#define OFF_NEED (OFF_WN   + (size_t)NB * NS)
#define OFF_LIST (OFF_NEED + (size_t)NU)
#define OFF_CNT  (OFF_LIST + (size_t)NEU)
#define SCRATCH_FLOATS (OFF_CNT + 4)

__device__ __align__(16) float g_scratch[SCRATCH_FLOATS];

// ---------------- PTX helpers -----------------------------------------------
__device__ __forceinline__ uint32_t smem_u32(const void* p) {
    uint32_t a;
    asm("{ .reg .u64 t; cvta.to.shared.u64 t, %1; cvt.u32.u64 %0, t; }" : "=r"(a) : "l"(p));
    return a;
}
#define SWZ128(o) ((o) ^ (((o) >> 3) & 0x70))

#define LDSM4(r, a) \
    asm volatile("ldmatrix.sync.aligned.m8n8.x4.shared.b16 {%0,%1,%2,%3}, [%4];" \
        : "=r"((r)[0]), "=r"((r)[1]), "=r"((r)[2]), "=r"((r)[3]) : "r"(a))

#define MMA_BF16(d, a, b) \
    asm volatile("mma.sync.aligned.m16n8k16.row.col.f32.bf16.bf16.f32 " \
        "{%0,%1,%2,%3}, {%4,%5,%6,%7}, {%8,%9}, {%0,%1,%2,%3};" \
        : "+f"((d)[0]), "+f"((d)[1]), "+f"((d)[2]), "+f"((d)[3]) \
        : "r"((a)[0]), "r"((a)[1]), "r"((a)[2]), "r"((a)[3]), "r"((b)[0]), "r"((b)[1]))

__device__ __forceinline__ void cp16(uint32_t dst, const void* src, bool ok) {
    asm volatile("cp.async.cg.shared.global [%0], [%1], 16, %2;"
                 :: "r"(dst), "l"(src), "r"(ok ? 16 : 0) : "memory");
}
__device__ __forceinline__ void cp_commit() { asm volatile("cp.async.commit_group;" ::: "memory"); }
__device__ __forceinline__ void cp_wait2()  { asm volatile("cp.async.wait_group 2;" ::: "memory"); }
__device__ __forceinline__ void cp_wait1()  { asm volatile("cp.async.wait_group 1;" ::: "memory"); }
__device__ __forceinline__ void cp_wait0()  { asm volatile("cp.async.wait_group 0;" ::: "memory"); }
#define CLUSTER_SYNC() do { \
    asm volatile("barrier.cluster.arrive.aligned;" ::: "memory"); \
    asm volatile("barrier.cluster.wait.aligned;" ::: "memory"); \
} while (0)

// ---------------- small kernels ----------------------------------------------
__global__ void mark_k(const int* __restrict__ uid, int* __restrict__ needed, int* __restrict__ count) {
    int i = blockIdx.x * blockDim.x + threadIdx.x;
    if (i == 0) *count = 0;
    if (i < NB) needed[uid[i]] = 1;
}
__global__ void compact_k(const int* __restrict__ row, const int* __restrict__ needed,
                          int* __restrict__ list, int* __restrict__ count) {
    int e = blockIdx.x * blockDim.x + threadIdx.x;
    bool keep = false;
    if (e < NEU) keep = (needed[row[e]] != 0);
    unsigned mask = __ballot_sync(0xFFFFFFFFu, keep);
    if (keep) {
        int lane = threadIdx.x & 31;
        int leader = __ffs(mask) - 1;
        int base = 0;
        if (lane == leader) base = atomicAdd(count, __popc(mask));
        base = __shfl_sync(mask, base, leader);
        list[base + __popc(mask & ((1u << lane) - 1))] = e;
    }
}
__global__ void split3_k(const float* __restrict__ a, const float* __restrict__ b,
                         const float* __restrict__ c,
                         __nv_bfloat16* __restrict__ ah, __nv_bfloat16* __restrict__ am,
                         __nv_bfloat16* __restrict__ bh, __nv_bfloat16* __restrict__ bm,
                         __nv_bfloat16* __restrict__ ch, __nv_bfloat16* __restrict__ cm) {
    int i = blockIdx.x * blockDim.x + threadIdx.x;
    const int NA = NH * NH, NBB = NH * NH, NC = NL * 3 * NH;
    const float* src;
    __nv_bfloat16 *hi, *mi;
    int j;
    if (i < NA) { src = a; hi = ah; mi = am; j = i; }
    else if (i < NA + NBB) { src = b; hi = bh; mi = bm; j = i - NA; }
    else if (i < NA + NBB + NC) { src = c; hi = ch; mi = cm; j = i - NA - NBB; }
    else return;
    float x = src[j];
    __nv_bfloat16 h = __float2bfloat16(x);
    hi[j] = h;
    mi[j] = __float2bfloat16(x - __bfloat162float(h));
}
__global__ void split_enc_k(const float* __restrict__ src, __nv_bfloat16* __restrict__ hi,
                            __nv_bfloat16* __restrict__ mi, int n) {
    int i = blockIdx.x * blockDim.x + threadIdx.x;
    if (i < n) {
        float x = src[i];
        __nv_bfloat16 h = __float2bfloat16(x);
        hi[i] = h;
        mi[i] = __float2bfloat16(x - __bfloat162float(h));
    }
}

// ---------------- loc scatter: 32 threads/edge, 8 floats/thread -------------
__global__ void scatter_loc_k(const int* __restrict__ row, const int* __restrict__ col,
                              const float* __restrict__ vals, const float* __restrict__ emb,
                              float* __restrict__ out) {
    int t = blockIdx.x * blockDim.x + threadIdx.x;
    int e = t >> 5;
    if (e >= NEL) return;
    int q = (t & 31) << 2;
    int r = row[e], cl = col[e];
    float v = vals[e];
    const float* src = emb + (size_t)cl * NH + q;
    float* dst = out + (size_t)r * NH + q;
    float4 x0 = *(const float4*)(src);
    float4 x1 = *(const float4*)(src + 128);
    asm volatile("red.global.add.v4.f32 [%0], {%1, %2, %3, %4};"
                 :: "l"(dst), "f"(v * x0.x), "f"(v * x0.y), "f"(v * x0.z), "f"(v * x0.w) : "memory");
    asm volatile("red.global.add.v4.f32 [%0], {%1, %2, %3, %4};"
                 :: "l"(dst + 128), "f"(v * x1.x), "f"(v * x1.y), "f"(v * x1.z), "f"(v * x1.w) : "memory");
}
__global__ void scatter_usr_c(const int* __restrict__ row, const int* __restrict__ col,
                              const float* __restrict__ vals, const float* __restrict__ emb,
                              float* __restrict__ out, const int* __restrict__ list,
                              const int* __restrict__ count) {
    int n = *count;
    int nb = (n + 3) >> 2;
    int sub = threadIdx.x >> 6;
    int q = (threadIdx.x & 63) << 2;
    for (int b = blockIdx.x; b < nb; b += gridDim.x) {
        int idx = b * 4 + sub;
        if (idx >= n) continue;
        int e = list[idx];
        int r = row[e], cl = col[e];
        float v = vals[e];
        float4 x = *(const float4*)(emb + (size_t)cl * NH + q);
        float* dst = out + (size_t)r * NH + q;
        asm volatile("red.global.add.v4.f32 [%0], {%1, %2, %3, %4};"
                     :: "l"(dst), "f"(v * x.x), "f"(v * x.y), "f"(v * x.z), "f"(v * x.w) : "memory");
    }
}

// ---------------- similarity only (x_emb no longer materialized) ------------
__global__ void gather_sim_k(const int* __restrict__ fsm, const int* __restrict__ uid,
                             const float* __restrict__ encw, const float* __restrict__ ewu,
                             float* __restrict__ sim) {
    int tid = threadIdx.x;
    int lane = tid & 31;
    int pair = blockIdx.x * 8 + (tid >> 5);
    int b = pair / NS;
    int loc = fsm[pair];
    const float* xr = encw + (size_t)loc * NH + lane * 8;
    const float* ur = ewu + (size_t)uid[b] * NH + lane * 8;
    float ss = 0.0f;
#pragma unroll
    for (int g = 0; g < 2; g++) {
        float4 x = *(const float4*)(xr + g * 4);
        float4 u = *(const float4*)(ur + g * 4);
        float d0 = u.x - x.x, d1 = u.y - x.y, d2 = u.z - x.z, d3 = u.w - x.w;
        ss += d0 * d0 + d1 * d1 + d2 * d2 + d3 * d3;
    }
#pragma unroll
    for (int o = 16; o > 0; o >>= 1) ss += __shfl_xor_sync(0xFFFFFFFFu, ss, o);
    if (lane == 0) sim[pair] = expf(-sqrtf(ss));
}

// ---------------- decay weights ---------------------------------------------
__global__ void weights_k(const float* __restrict__ td, const float* __restrict__ gd,
                          const float* __restrict__ sim, const int* __restrict__ length,
                          float* __restrict__ wn) {
    int b = blockIdx.x;
    int s = threadIdx.x;
    __shared__ float red[128];
    float w = 0.0f;
    if (s < NS) {
        float t = td[b * NS + s];
        float a = (cosf(t * (6.2831853071795864769f / 86400.0f)) + 1.0f) * 0.5f
                  * expf(-t * (0.1f / 86400.0f));
        float bb = expf(-gd[b * NS + s] * 1000.0f);
        w = (a * bb + 1e-10f) * sim[b * NS + s];
        if (s >= length[b]) w = 0.0f;
    }
    red[s] = w;
    __syncthreads();
    for (int o = 64; o > 0; o >>= 1) {
        if (s < o) red[s] += red[s + o];
        __syncthreads();
    }
    float denom = red[0];
    if (s < NS) wn[b * NS + s] = w / denom;
}

// ---------------- mma.sync bf16x3 GEMM (3-stage pipeline) -------------------
#define STG_B 65536
#define SMEM_GEMM (3 * STG_B)

__global__ __launch_bounds__(256, 1)
void gemm3(const __nv_bfloat16* __restrict__ Ah, const __nv_bfloat16* __restrict__ Am,
           const __nv_bfloat16* __restrict__ Bh, const __nv_bfloat16* __restrict__ Bm,
           int Nlog, int K, float* __restrict__ C, const float* __restrict__ bias) {
    extern __shared__ char smem[];
    uint32_t sb = smem_u32(smem);
    int tid = threadIdx.x;
    int lane = tid & 31;
    int wid = tid >> 5;
    int wm = wid >> 2, wn = wid & 3;
    int m0 = blockIdx.x * 128;
    int n0 = blockIdx.y * 128;
    int nc = K >> 6;

    const __nv_bfloat16* bases[4] = {Ah, Am, Bh, Bm};
    auto load_chunk = [&](int stage, int c) {
#pragma unroll
        for (int i = 0; i < 16; i++) {
            int seg = tid + i * 256;
            int arr = seg >> 10;
            int rem = seg & 1023;
            int row = rem >> 3;
            int c16 = rem & 7;
            uint32_t dst = sb + stage * STG_B + arr * 16384 + SWZ128(row * 128 + c16 * 16);
            int rg = (arr < 2) ? (m0 + row) : (n0 + row);
            bool ok = (arr < 2) || (rg < Nlog);
            cp16(dst, bases[arr] + (size_t)rg * K + c * 64 + c16 * 8, ok);
        }
        cp_commit();
    };

    float acc[4][4][4];
#pragma unroll
    for (int a = 0; a < 4; a++)
#pragma unroll
        for (int b = 0; b < 4; b++)
#pragma unroll
            for (int d = 0; d < 4; d++) acc[a][b][d] = 0.0f;

    int lrow = lane & 15;
    int lchunk = lane >> 4;

    load_chunk(0, 0);
    load_chunk(1, 1);
    for (int c = 0; c < nc; c++) {
        if (c + 2 < nc) { load_chunk((c + 2) % 3, c + 2); cp_wait2(); }
        else if (c + 1 < nc) cp_wait1();
        else cp_wait0();
        __syncthreads();
        uint32_t stg = sb + (c % 3) * STG_B;
#pragma unroll
        for (int s = 0; s < 4; s++) {
            uint32_t ah[4][4], am[4][4];
#pragma unroll
            for (int mt = 0; mt < 4; mt++) {
                int r = wm * 64 + mt * 16 + lrow;
                uint32_t off = SWZ128(r * 128 + (s * 2 + lchunk) * 16);
                LDSM4(ah[mt], stg + off);
                LDSM4(am[mt], stg + 16384 + off);
            }
            uint32_t bh[4][2], bm[4][2];
#pragma unroll
            for (int g = 0; g < 2; g++) {
                int r = wn * 32 + g * 16 + lrow;
                uint32_t off = SWZ128(r * 128 + (s * 2 + lchunk) * 16);
                uint32_t q[4];
                LDSM4(q, stg + 32768 + off);
                bh[2 * g][0] = q[0]; bh[2 * g + 1][0] = q[1];
                bh[2 * g][1] = q[2]; bh[2 * g + 1][1] = q[3];
                LDSM4(q, stg + 49152 + off);
                bm[2 * g][0] = q[0]; bm[2 * g + 1][0] = q[1];
                bm[2 * g][1] = q[2]; bm[2 * g + 1][1] = q[3];
            }
#pragma unroll
            for (int mt = 0; mt < 4; mt++)
#pragma unroll
                for (int nt = 0; nt < 4; nt++) {
                    MMA_BF16(acc[mt][nt], ah[mt], bh[nt]);
                    MMA_BF16(acc[mt][nt], ah[mt], bm[nt]);
                    MMA_BF16(acc[mt][nt], am[mt], bh[nt]);
                }
        }
        __syncthreads();
    }

#pragma unroll
    for (int mt = 0; mt < 4; mt++) {
        int r0 = m0 + wm * 64 + mt * 16 + (lane >> 2);
#pragma unroll
        for (int nt = 0; nt < 4; nt++) {
            int nn = n0 + wn * 32 + nt * 8 + (lane & 3) * 2;
            if (nn < Nlog) {
                float b0 = bias[nn], b1 = bias[nn + 1];
                float2 v0 = make_float2(acc[mt][nt][0] + b0, acc[mt][nt][1] + b1);
                *(float2*)(C + (size_t)r0 * Nlog + nn) = v0;
                float2 v1 = make_float2(acc[mt][nt][2] + b0, acc[mt][nt][3] + b1);
                *(float2*)(C + (size_t)(r0 + 8) * Nlog + nn) = v1;
            }
        }
    }
}

// ---------------- clustered persistent RNN (R14 structure + encp gather) ----
// 2-CTA clusters, rank r computes h cols [128r,128r+128). Wh+Wm halves
// resident; per-step xp fragment gathered from encp[fsm[m,s]] (L2-resident).
#define R2_AH0 0
#define R2_AM0 8192
#define R2_AH1 16384
#define R2_AM1 24576
#define R2_WH  32768
#define R2_WM  (R2_WH + 65536)
#define R2_WNS (R2_WM + 65536)
#define R2_FSM (R2_WNS + 16 * NS * 4)
#define SMEM_RNN2 (R2_FSM + 16 * NS * 4)

__global__ __launch_bounds__(256, 1)
void rnn_persist2(const __nv_bfloat16* __restrict__ whh_h, const __nv_bfloat16* __restrict__ whh_m,
                  const float* __restrict__ encp, const int* __restrict__ fsm,
                  const float* __restrict__ wn, const float* __restrict__ b_hh,
                  const float* __restrict__ h0,
                  __nv_bfloat16* __restrict__ fh, __nv_bfloat16* __restrict__ fm) {
    extern __shared__ char smem[];
    uint32_t sb = smem_u32(smem);
    int tid = threadIdx.x;
    int lane = tid & 31;
    int wid = tid >> 5;
    uint32_t rank;
    asm("mov.u32 %0, %%cluster_ctarank;" : "=r"(rank));
    int m0 = (blockIdx.x >> 1) * 16;
    int nhalf = rank * 128;
    float* wns = (float*)(smem + R2_WNS);
    int* fsmc = (int*)(smem + R2_FSM);

    uint32_t psb;
    asm("mapa.shared::cluster.u32 %0, %1, %2;" : "=r"(psb) : "r"(sb), "r"(rank ^ 1u));

    // resident Wh + Wm halves: rows [nhalf, nhalf+128), 4 K-chunks x 16KB each
#pragma unroll
    for (int i = 0; i < 16; i++) {
        int seg = tid + i * 256;
        int ch = seg >> 10;
        int rem = seg & 1023;
        int row = rem >> 3;
        int c16 = rem & 7;
        uint32_t off = ch * 16384 + SWZ128(row * 128 + c16 * 16);
        cp16(sb + R2_WH + off, whh_h + (size_t)(nhalf + row) * NH + ch * 64 + c16 * 8, true);
        cp16(sb + R2_WM + off, whh_m + (size_t)(nhalf + row) * NH + ch * 64 + c16 * 8, true);
    }
    cp_commit();

    for (int i = tid; i < 16 * NS; i += 256) {
        int r = i / NS, s = i % NS;
        wns[r * NS + s] = wn[(m0 + r) * NS + s];
        fsmc[r * NS + s] = fsm[(m0 + r) * NS + s];
    }
    // h0 (full 256 cols) into buffer 0
    for (int i = tid; i < 16 * NH; i += 256) {
        int r = i >> 8, cc = i & 255;
        float x = h0[(size_t)(m0 + r) * NH + cc];
        __nv_bfloat16 hh = __float2bfloat16(x);
        uint32_t off = (cc >> 6) * 2048 + SWZ128(r * 128 + (cc & 63) * 2);
        *(__nv_bfloat16*)(smem + R2_AH0 + off) = hh;
        *(__nv_bfloat16*)(smem + R2_AM0 + off) = __float2bfloat16(x - __bfloat162float(hh));
    }

    float bias_r[4];
#pragma unroll
    for (int nt = 0; nt < 2; nt++) {
        int n = nhalf + wid * 16 + nt * 8 + (lane & 3) * 2;
        bias_r[nt * 2 + 0] = b_hh[n];
        bias_r[nt * 2 + 1] = b_hh[n + 1];
    }

    cp_wait0();
    __syncthreads();

    float acc_out[2][4];
#pragma unroll
    for (int a = 0; a < 2; a++)
#pragma unroll
        for (int d = 0; d < 4; d++) acc_out[a][d] = 0.0f;

    int lrow = lane & 15;
    int lchunk = lane >> 4;
    int r0 = lane >> 2;

    for (int s = 0; s < NS; s++) {
        uint32_t abase = (s & 1) ? (uint32_t)R2_AH1 : (uint32_t)R2_AH0;
        uint32_t wbase = (s & 1) ? (uint32_t)R2_AH0 : (uint32_t)R2_AH1;
        // gather per-step xp fragment from encp (issued early, consumed in epilogue)
        int loc0 = fsmc[r0 * NS + s];
        int loc1 = fsmc[(r0 + 8) * NS + s];
        float2 xpr[2][2];
#pragma unroll
        for (int nt = 0; nt < 2; nt++) {
            int n = nhalf + wid * 16 + nt * 8 + (lane & 3) * 2;
            xpr[nt][0] = *(const float2*)(encp + (size_t)loc0 * NH + n);
            xpr[nt][1] = *(const float2*)(encp + (size_t)loc1 * NH + n);
        }
        float acc[2][4];
#pragma unroll
        for (int a = 0; a < 2; a++)
#pragma unroll
            for (int d = 0; d < 4; d++) acc[a][d] = 0.0f;

#pragma unroll
        for (int c = 0; c < 4; c++) {
            uint32_t stWh = sb + R2_WH + c * 16384;
            uint32_t stWm = sb + R2_WM + c * 16384;
#pragma unroll
            for (int s4 = 0; s4 < 4; s4++) {
                uint32_t aoff = c * 2048 + SWZ128(lrow * 128 + (s4 * 2 + lchunk) * 16);
                uint32_t ah[4], am[4];
                LDSM4(ah, sb + abase + aoff);
                LDSM4(am, sb + abase + 8192 + aoff);
                uint32_t off = SWZ128((wid * 16 + lrow) * 128 + (s4 * 2 + lchunk) * 16);
                uint32_t bh[2][2], bm[2][2];
                uint32_t q[4];
                LDSM4(q, stWh + off);
                bh[0][0] = q[0]; bh[1][0] = q[1]; bh[0][1] = q[2]; bh[1][1] = q[3];
                LDSM4(q, stWm + off);
                bm[0][0] = q[0]; bm[1][0] = q[1]; bm[0][1] = q[2]; bm[1][1] = q[3];
#pragma unroll
                for (int nt = 0; nt < 2; nt++) {
                    MMA_BF16(acc[nt], ah, bh[nt]);
                    MMA_BF16(acc[nt], ah, bm[nt]);
                    MMA_BF16(acc[nt], am, bh[nt]);
                }
            }
        }

        float w0 = wns[r0 * NS + s];
        float w1 = wns[(r0 + 8) * NS + s];
#pragma unroll
        for (int nt = 0; nt < 2; nt++) {
            int cc = nhalf + wid * 16 + nt * 8 + (lane & 3) * 2;
            float v00 = tanhf(acc[nt][0] + xpr[nt][0].x + bias_r[nt * 2 + 0]);
            float v01 = tanhf(acc[nt][1] + xpr[nt][0].y + bias_r[nt * 2 + 1]);
            float v10 = tanhf(acc[nt][2] + xpr[nt][1].x + bias_r[nt * 2 + 0]);
            float v11 = tanhf(acc[nt][3] + xpr[nt][1].y + bias_r[nt * 2 + 1]);
            acc_out[nt][0] += v00 * w0;
            acc_out[nt][1] += v01 * w0;
            acc_out[nt][2] += v10 * w1;
            acc_out[nt][3] += v11 * w1;
            __nv_bfloat16 h00 = __float2bfloat16(v00), h01 = __float2bfloat16(v01);
            __nv_bfloat16 h10 = __float2bfloat16(v10), h11 = __float2bfloat16(v11);
            __nv_bfloat162 p0; p0.x = h00; p0.y = h01;
            __nv_bfloat162 p1; p1.x = h10; p1.y = h11;
            __nv_bfloat162 q0; q0.x = __float2bfloat16(v00 - __bfloat162float(h00));
                               q0.y = __float2bfloat16(v01 - __bfloat162float(h01));
            __nv_bfloat162 q1; q1.x = __float2bfloat16(v10 - __bfloat162float(h10));
                               q1.y = __float2bfloat16(v11 - __bfloat162float(h11));
            uint32_t off0 = (cc >> 6) * 2048 + SWZ128(r0 * 128 + (cc & 63) * 2);
            uint32_t off1 = (cc >> 6) * 2048 + SWZ128((r0 + 8) * 128 + (cc & 63) * 2);
            uint32_t up0 = *(uint32_t*)&p0, up1 = *(uint32_t*)&p1;
            uint32_t uq0 = *(uint32_t*)&q0, uq1 = *(uint32_t*)&q1;
            *(uint32_t*)(smem + wbase + off0) = up0;
            *(uint32_t*)(smem + wbase + off1) = up1;
            *(uint32_t*)(smem + wbase + 8192 + off0) = uq0;
            *(uint32_t*)(smem + wbase + 8192 + off1) = uq1;
            asm volatile("st.shared::cluster.b32 [%0], %1;" :: "r"(psb + wbase + off0), "r"(up0) : "memory");
            asm volatile("st.shared::cluster.b32 [%0], %1;" :: "r"(psb + wbase + off1), "r"(up1) : "memory");
            asm volatile("st.shared::cluster.b32 [%0], %1;" :: "r"(psb + wbase + 8192 + off0), "r"(uq0) : "memory");
            asm volatile("st.shared::cluster.b32 [%0], %1;" :: "r"(psb + wbase + 8192 + off1), "r"(uq1) : "memory");
        }
        CLUSTER_SYNC();
    }

#pragma unroll
    for (int nt = 0; nt < 2; nt++) {
        int n = nhalf + wid * 16 + nt * 8 + (lane & 3) * 2;
#pragma unroll
        for (int rr = 0; rr < 2; rr++) {
            int m = m0 + r0 + rr * 8;
            float v0 = acc_out[nt][rr * 2 + 0];
            float v1 = acc_out[nt][rr * 2 + 1];
            __nv_bfloat16 h0b = __float2bfloat16(v0), h1b = __float2bfloat16(v1);
            fh[(size_t)m * 3 * NH + n] = h0b;
            fh[(size_t)m * 3 * NH + n + 1] = h1b;
            fm[(size_t)m * 3 * NH + n] = __float2bfloat16(v0 - __bfloat162float(h0b));
            fm[(size_t)m * 3 * NH + n + 1] = __float2bfloat16(v1 - __bfloat162float(h1b));
        }
    }
}

// ---------------- fused out_w2 + p_u ----------------------------------------
__global__ void outw2_pu_k(const int* __restrict__ fseq, const float* __restrict__ emb2,
                           const float* __restrict__ wn, const int* __restrict__ uid,
                           const float* __restrict__ user_emb,
                           __nv_bfloat16* __restrict__ fh, __nv_bfloat16* __restrict__ fm) {
    int b = blockIdx.x;
    int h = threadIdx.x;
    float x = user_emb[(size_t)uid[b] * NH + h];
    __nv_bfloat16 ph = __float2bfloat16(x);
    fh[(size_t)b * 3 * NH + NH + h] = ph;
    fm[(size_t)b * 3 * NH + NH + h] = __float2bfloat16(x - __bfloat162float(ph));
    float acc = 0.0f;
    for (int s = 0; s < NS; s++) {
        int loc = fseq[b * NS + s];
        acc += emb2[(size_t)loc * NH + h] * wn[b * NS + s];
    }
    __nv_bfloat16 hh = __float2bfloat16(acc);
    fh[(size_t)b * 3 * NH + 2 * NH + h] = hh;
    fm[(size_t)b * 3 * NH + 2 * NH + h] = __float2bfloat16(acc - __bfloat162float(hh));
}

// ---------------- host launcher ---------------------------------------------
extern "C" void kernel_launch(void* const* d_in, const int* in_sizes, int n_in,
                              void* d_out, int out_size) {
    const int*   full_seq     = (const int*)d_in[0];
    const int*   full_seq_map = (const int*)d_in[1];
    const int*   length       = (const int*)d_in[2];
    const int*   user_id      = (const int*)d_in[3];
    const float* time_delta   = (const float*)d_in[4];
    const float* geo_delta    = (const float*)d_in[5];
    const float* enc_emb      = (const float*)d_in[6];
    const float* user_emb     = (const float*)d_in[7];
    const float* emb2         = (const float*)d_in[8];
    const int*   row_loc      = (const int*)d_in[9];
    const int*   col_loc      = (const int*)d_in[10];
    const float* vals_loc     = (const float*)d_in[11];
    const int*   row_usr      = (const int*)d_in[12];
    const int*   col_usr      = (const int*)d_in[13];
    const float* vals_usr     = (const float*)d_in[14];
    const float* W_ih         = (const float*)d_in[15];
    const float* W_hh         = (const float*)d_in[16];
    const float* b_ih         = (const float*)d_in[17];
    const float* b_hh         = (const float*)d_in[18];
    const float* W1           = (const float*)d_in[19];
    const float* b1           = (const float*)d_in[20];
    const float* h0           = (const float*)d_in[21];
    float* out = (float*)d_out;

    float* base = nullptr;
    cudaGetSymbolAddress((void**)&base, g_scratch);
    float* encw = base + OFF_ENCW;
    float* ewu  = base + OFF_EWU;
    __nv_bfloat16* ench = (__nv_bfloat16*)(base + OFF_ENCH);
    __nv_bfloat16* encm = (__nv_bfloat16*)(base + OFF_ENCM);
    float* encp = base + OFF_ENCP;
    __nv_bfloat16* w1h = (__nv_bfloat16*)(base + OFF_W1H);
    __nv_bfloat16* w1m = (__nv_bfloat16*)(base + OFF_W1M);
    __nv_bfloat16* wih = (__nv_bfloat16*)(base + OFF_WIHH);
    __nv_bfloat16* wim = (__nv_bfloat16*)(base + OFF_WIHM);
    __nv_bfloat16* whh = (__nv_bfloat16*)(base + OFF_WHHH);
    __nv_bfloat16* whm = (__nv_bfloat16*)(base + OFF_WHHM);
    __nv_bfloat16* fh  = (__nv_bfloat16*)(base + OFF_FH);
    __nv_bfloat16* fm  = (__nv_bfloat16*)(base + OFF_FM);
    float* sim  = base + OFF_SIM;
    float* wn   = base + OFF_WN;
    int*   needed = (int*)(base + OFF_NEED);
    int*   elist  = (int*)(base + OFF_LIST);
    int*   ecount = (int*)(base + OFF_CNT);

    static cudaStream_t s1 = nullptr, s2 = nullptr;
    static cudaEvent_t evRoot = nullptr, evA = nullptr, evB = nullptr,
                       evC = nullptr, evE = nullptr, evF = nullptr;
    if (s1 == nullptr) {
        cudaStreamCreateWithFlags(&s1, cudaStreamNonBlocking);
        cudaStreamCreateWithFlags(&s2, cudaStreamNonBlocking);
        cudaEventCreateWithFlags(&evRoot, cudaEventDisableTiming);
        cudaEventCreateWithFlags(&evA, cudaEventDisableTiming);
        cudaEventCreateWithFlags(&evB, cudaEventDisableTiming);
        cudaEventCreateWithFlags(&evC, cudaEventDisableTiming);
        cudaEventCreateWithFlags(&evE, cudaEventDisableTiming);
        cudaEventCreateWithFlags(&evF, cudaEventDisableTiming);
        cudaFuncSetAttribute(gemm3, cudaFuncAttributeMaxDynamicSharedMemorySize, SMEM_GEMM);
        cudaFuncSetAttribute(rnn_persist2, cudaFuncAttributeMaxDynamicSharedMemorySize, SMEM_RNN2);
    }

    // s0: zero accumulators, then fork
    cudaMemsetAsync(encw, 0, 2 * (size_t)NL * NH * sizeof(float), 0);
    cudaMemsetAsync(needed, 0, (size_t)NU * sizeof(int), 0);
    cudaEventRecord(evRoot, 0);
    cudaStreamWaitEvent(s1, evRoot, 0);
    cudaStreamWaitEvent(s2, evRoot, 0);

    // s2: weight splits
    {
        int n = 2 * NH * NH + NL * 3 * NH;
        split3_k<<<(n + 255) / 256, 256, 0, s2>>>(W_ih, W_hh, W1, wih, wim, whh, whm, w1h, w1m);
    }
    cudaEventRecord(evC, s2);

    // s1: loc scatter -> split encw -> encp GEMM (needs wih from s2)
    scatter_loc_k<<<(NEL * 32 + 255) / 256, 256, 0, s1>>>(row_loc, col_loc, vals_loc, enc_emb, encw);
    cudaEventRecord(evA, s1);
    split_enc_k<<<(NL * NH + 255) / 256, 256, 0, s1>>>(encw, ench, encm, NL * NH);
    cudaStreamWaitEvent(s1, evC, 0);
    gemm3<<<dim3(NLP / 128, 2), 256, SMEM_GEMM, s1>>>(ench, encm, wih, wim, NH, NH, encp, b_ih);
    cudaEventRecord(evE, s1);

    // s0: user-graph chain
    mark_k<<<(NB + 255) / 256, 256>>>(user_id, needed, ecount);
    compact_k<<<(NEU + 255) / 256, 256>>>(row_usr, needed, elist, ecount);
    scatter_usr_c<<<2048, 256>>>(row_usr, col_usr, vals_usr, enc_emb, ewu, elist, ecount);

    // s0: wait scatter_loc (encw) -> sim + weights
    cudaStreamWaitEvent(0, evA, 0);
    gather_sim_k<<<NB * NS / 8, 256>>>(full_seq_map, user_id, encw, ewu, sim);
    weights_k<<<NB, 128>>>(time_delta, geo_delta, sim, length, wn);
    cudaEventRecord(evB, 0);

    // s2: outw2+pu (needs wn; writes feat cols [NH, 3NH))
    cudaStreamWaitEvent(s2, evB, 0);
    outw2_pu_k<<<NB, NH, 0, s2>>>(full_seq, emb2, wn, user_id, user_emb, fh, fm);
    cudaEventRecord(evF, s2);

    // s0: wait weight splits + encp, then clustered RNN (feat cols [0, NH))
    cudaStreamWaitEvent(0, evC, 0);
    cudaStreamWaitEvent(0, evE, 0);
    {
        cudaLaunchConfig_t cfg = {};
        cfg.gridDim = dim3(NB / 16 * 2, 1, 1);
        cfg.blockDim = dim3(256, 1, 1);
        cfg.dynamicSmemBytes = SMEM_RNN2;
        cfg.stream = 0;
        cudaLaunchAttribute attrs[1];
        attrs[0].id = cudaLaunchAttributeClusterDimension;
        attrs[0].val.clusterDim = {2, 1, 1};
        cfg.attrs = attrs;
        cfg.numAttrs = 1;
        cudaLaunchKernelEx(&cfg, rnn_persist2, whh, whm, (const float*)encp, full_seq_map,
                           (const float*)wn, b_hh, h0, fh, fm);
    }

    // s0: wait outw2_pu, then final GEMM
    cudaStreamWaitEvent(0, evF, 0);
    gemm3<<<dim3(NB / 128, (NL + 127) / 128), 256, SMEM_GEMM>>>(fh, fm, w1h, w1m, NL, 3 * NH, out, b1);
}